// round 6
// baseline (speedup 1.0000x reference)
#include <cuda_runtime.h>
#include <cuda_bf16.h>
#include <math.h>

// Problem constants
#define BB 64
#define TT 128
#define TS 127          // timesteps = T-1
#define VV 10000
#define EE 300
#define HH 1024
#define G4 4096         // 4*H
#define KT 32           // k-tile depth for step kernel

typedef unsigned long long u64;

// ---------------- scratch (static device memory; no allocations) -------------
__device__ float g_pre0[(size_t)TS * BB * G4];     // x@w_ih0 + b0, row = t*64+b
__device__ float g_h1all[(size_t)TS * BB * HH];    // all layer-1 hidden states
__device__ float g_h0buf[2][BB * HH];
__device__ float g_c0[BB * HH];
__device__ float g_c1[BB * HH];
__device__ float g_part[2][BB * G4];               // layer1 ih-partial, dbl buffered
__device__ float g_rowloss[TS * BB];

__device__ __forceinline__ float sigmoidf_(float x) {
    return 1.0f / (1.0f + expf(-x));
}
__device__ __forceinline__ u64 fma2_(u64 a, u64 b, u64 c) {
    u64 d; asm("fma.rn.f32x2 %0, %1, %2, %3;" : "=l"(d) : "l"(a), "l"(b), "l"(c));
    return d;
}
__device__ __forceinline__ float2 unpack2_(u64 a) {
    float2 f; asm("mov.b64 {%0, %1}, %2;" : "=f"(f.x), "=f"(f.y) : "l"(a));
    return f;
}

// ---------------- init: zero recurrent state every replay --------------------
__global__ void init_state_kernel() {
    int i = blockIdx.x * blockDim.x + threadIdx.x;
    if (i < BB * HH) { g_h0buf[0][i] = 0.f; g_c0[i] = 0.f; g_c1[i] = 0.f; }
}

// ---------------- pre0 = gather(emb) @ w_ih0 + b0 ----------------------------
__global__ __launch_bounds__(256) void pre0_gemm_kernel(
    const int* __restrict__ sent, const float* __restrict__ wordvec,
    const float* __restrict__ w_ih0, const float* __restrict__ b0)
{
    __shared__ float As[4][64];
    __shared__ float Bs[4][64];
    const int t = blockIdx.y;
    const int colBase = blockIdx.x * 64;
    const int tid = threadIdx.x;
    const int tx = tid & 15, ty = tid >> 4;

    const float* arow = nullptr;
    if (tid < 64) {
        int token = sent[tid * TT + t];
        arow = wordvec + (size_t)token * EE;
    }
    const int bRow = tid >> 6, bCol = tid & 63;

    float acc[4][4] = {};
    for (int kt = 0; kt < 75; kt++) {
        __syncthreads();
        if (tid < 64) {
            float4 a = *(const float4*)(arow + kt * 4);
            As[0][tid] = a.x; As[1][tid] = a.y; As[2][tid] = a.z; As[3][tid] = a.w;
        }
        Bs[bRow][bCol] = w_ih0[(size_t)(kt * 4 + bRow) * G4 + colBase + bCol];
        __syncthreads();
#pragma unroll
        for (int k = 0; k < 4; k++) {
            float4 a4 = *(const float4*)&As[k][ty * 4];
            float4 b4 = *(const float4*)&Bs[k][tx * 4];
            acc[0][0] += a4.x * b4.x; acc[0][1] += a4.x * b4.y; acc[0][2] += a4.x * b4.z; acc[0][3] += a4.x * b4.w;
            acc[1][0] += a4.y * b4.x; acc[1][1] += a4.y * b4.y; acc[1][2] += a4.y * b4.z; acc[1][3] += a4.y * b4.w;
            acc[2][0] += a4.z * b4.x; acc[2][1] += a4.z * b4.y; acc[2][2] += a4.z * b4.z; acc[2][3] += a4.z * b4.w;
            acc[3][0] += a4.w * b4.x; acc[3][1] += a4.w * b4.y; acc[3][2] += a4.w * b4.z; acc[3][3] += a4.w * b4.w;
        }
    }
    float* dst = g_pre0 + ((size_t)t * 64) * G4 + colBase;
#pragma unroll
    for (int i = 0; i < 4; i++) {
        int b_ = ty * 4 + i;
#pragma unroll
        for (int j = 0; j < 4; j++) {
            int c = tx * 4 + j;
            dst[(size_t)b_ * G4 + c] = acc[i][j] + b0[colBase + c];
        }
    }
}

// ---------------- LSTM step v3: 3 pipelined groups, 384 CTAs ------------------
// Launch s (s = 0..128):
//   G0 (bid<128):        layer0 step t=s        (valid s<=126), K=1024
//   G1 (128<=bid<256):   part[s&1] = h0[s-1] @ w_ih1   (valid 1<=s<=127), K=1024
//   G2 (256<=bid<384):   h1[s-2] = PW(h1[s-3]@w_hh1 + part[(s-1)&1] + b1) (s>=2)
// Each CTA: 64 rows x 32 gate-cols (8 j x 4 gates), 256 threads, 4x2 f32x2 out.
// smem layout (floats): hbuf[2][KT][68] @0 (4352), wbuf[2][KT][66] @4352 (4224)
//                       gbuf[64][33] aliases hbuf after main loop.
__global__ __launch_bounds__(256) void step3_kernel(
    int s, const float* __restrict__ w_hh0, const float* __restrict__ w_ih1,
    const float* __restrict__ w_hh1, const float* __restrict__ b1)
{
    __shared__ __align__(16) float sm[4352 + 4224];

    const int grp = blockIdx.x >> 7;
    const int cb  = blockIdx.x & 127;
    const int j0  = cb * 8;
    const int tid = threadIdx.x;

    const float* hsrc = nullptr; const float* W = nullptr;
    bool doGemm = true;
    int t2 = s - 2;
    if (grp == 0) {
        if (s > 126) return;
        hsrc = g_h0buf[s & 1]; W = w_hh0;
    } else if (grp == 1) {
        if (s < 1 || s > 127) return;
        hsrc = g_h0buf[s & 1]; W = w_ih1;
    } else {
        if (s < 2) return;
        W = w_hh1;
        if (t2 > 0) hsrc = g_h1all + (size_t)(t2 - 1) * BB * HH;
        else doGemm = false;
    }

    // loader indices
    const int hrow = tid >> 2, hc = tid & 3;      // h: row 0..63, k-chunk
    const int wk = tid >> 3,  wc4 = tid & 7;      // w: k-row 0..31, col-quad
    // compute indices
    const int rg = tid & 15, cg = tid >> 4;
    const int r0 = rg * 4;

    u64 a00 = 0, a01 = 0, a10 = 0, a11 = 0;

    if (doGemm) {
        const float* hg = hsrc + hrow * HH;
        const float* wg = W + (size_t)wk * G4 + (wc4 >> 1) * HH + j0 + (wc4 & 1) * 4;

        float4 pA[3], pB[3];

        auto LD = [&](int k0, float4* p) {
            p[0] = *(const float4*)&hg[k0 + hc * 4];
            p[1] = *(const float4*)&hg[k0 + hc * 4 + 16];
            p[2] = *(const float4*)&wg[(size_t)k0 * G4];
        };
        auto ST = [&](int buf, const float4* p) {
            float* hb = sm + buf * (KT * 68);
            float* wb = sm + 4352 + buf * (KT * 66);
            hb[(hc * 4 + 0) * 68 + hrow] = p[0].x;
            hb[(hc * 4 + 1) * 68 + hrow] = p[0].y;
            hb[(hc * 4 + 2) * 68 + hrow] = p[0].z;
            hb[(hc * 4 + 3) * 68 + hrow] = p[0].w;
            hb[(hc * 4 + 16) * 68 + hrow] = p[1].x;
            hb[(hc * 4 + 17) * 68 + hrow] = p[1].y;
            hb[(hc * 4 + 18) * 68 + hrow] = p[1].z;
            hb[(hc * 4 + 19) * 68 + hrow] = p[1].w;
            float* wr_ = wb + wk * 66;
            *(float2*)&wr_[4 * wc4]      = make_float2(p[2].x, p[2].x);
            *(float2*)&wr_[32 + 4 * wc4] = make_float2(p[2].y, p[2].y);
            *(float2*)&wr_[4 * wc4 + 2]  = make_float2(p[2].z, p[2].z);
            *(float2*)&wr_[34 + 4 * wc4] = make_float2(p[2].w, p[2].w);
        };
        auto CP = [&](int buf) {
            const float* hb = sm + buf * (KT * 68);
            const float* wb = sm + 4352 + buf * (KT * 66);
#pragma unroll
            for (int k = 0; k < KT; k++) {
                ulonglong2 hp = *(const ulonglong2*)&hb[k * 68 + r0];
                u64 w0 = *(const u64*)&wb[k * 66 + 2 * cg];
                u64 w1 = *(const u64*)&wb[k * 66 + 32 + 2 * cg];
                a00 = fma2_(hp.x, w0, a00);
                a01 = fma2_(hp.x, w1, a01);
                a10 = fma2_(hp.y, w0, a10);
                a11 = fma2_(hp.y, w1, a11);
            }
        };

        LD(0, pA);
        ST(0, pA);          // tile 0 -> buf0
        LD(KT, pB);         // tile 1 in flight
        __syncthreads();
        for (int tl = 0; tl < 32; tl += 2) {
            if (tl + 2 < 32) LD((tl + 2) * KT, pA);
            CP(0);
            ST(1, pB);      // tile tl+1 -> buf1
            __syncthreads();
            if (tl + 3 < 32) LD((tl + 3) * KT, pB);
            CP(1);
            if (tl + 2 < 32) ST(0, pA);   // tile tl+2 -> buf0
            __syncthreads();
        }
    } else {
        __syncthreads();    // keep CTA-uniform barrier structure trivial
    }
    __syncthreads();

    // gates -> gbuf (aliases hbuf region)
    float* gb = sm;
    {
        float2 v;
        v = unpack2_(a00); gb[(r0 + 0) * 33 + 2 * cg] = v.x; gb[(r0 + 1) * 33 + 2 * cg] = v.y;
        v = unpack2_(a10); gb[(r0 + 2) * 33 + 2 * cg] = v.x; gb[(r0 + 3) * 33 + 2 * cg] = v.y;
        v = unpack2_(a01); gb[(r0 + 0) * 33 + 2 * cg + 1] = v.x; gb[(r0 + 1) * 33 + 2 * cg + 1] = v.y;
        v = unpack2_(a11); gb[(r0 + 2) * 33 + 2 * cg + 1] = v.x; gb[(r0 + 3) * 33 + 2 * cg + 1] = v.y;
    }
    __syncthreads();

    // pointwise: thread handles 2 (r, j) items. gbuf col = g*8 + jl.
    const int r = tid & 63;
    const int jq = tid >> 6;
    if (grp == 0) {
        const float* av = g_pre0 + ((size_t)s * BB + r) * G4;
        float* hout = g_h0buf[(s + 1) & 1];
#pragma unroll
        for (int jj = 0; jj < 2; jj++) {
            int jl = jq * 2 + jj, j = j0 + jl;
            float gi = gb[r * 33 + jl]      + av[j];
            float gf = gb[r * 33 + 8 + jl]  + av[HH + j];
            float gg = gb[r * 33 + 16 + jl] + av[2 * HH + j];
            float go = gb[r * 33 + 24 + jl] + av[3 * HH + j];
            float c  = g_c0[r * HH + j];
            float cn = sigmoidf_(gf) * c + sigmoidf_(gi) * tanhf(gg);
            float hn = sigmoidf_(go) * tanhf(cn);
            g_c0[r * HH + j] = cn;
            hout[r * HH + j] = hn;
        }
    } else if (grp == 1) {
        float* pp = g_part[s & 1] + (size_t)r * G4;
#pragma unroll
        for (int jj = 0; jj < 2; jj++) {
            int jl = jq * 2 + jj, j = j0 + jl;
            pp[j]          = gb[r * 33 + jl];
            pp[HH + j]     = gb[r * 33 + 8 + jl];
            pp[2 * HH + j] = gb[r * 33 + 16 + jl];
            pp[3 * HH + j] = gb[r * 33 + 24 + jl];
        }
    } else {
        const float* pp = g_part[(s - 1) & 1] + (size_t)r * G4;
        float* hout = g_h1all + (size_t)t2 * BB * HH;
#pragma unroll
        for (int jj = 0; jj < 2; jj++) {
            int jl = jq * 2 + jj, j = j0 + jl;
            float gi = gb[r * 33 + jl]      + pp[j]          + b1[j];
            float gf = gb[r * 33 + 8 + jl]  + pp[HH + j]     + b1[HH + j];
            float gg = gb[r * 33 + 16 + jl] + pp[2 * HH + j] + b1[2 * HH + j];
            float go = gb[r * 33 + 24 + jl] + pp[3 * HH + j] + b1[3 * HH + j];
            float c  = g_c1[r * HH + j];
            float cn = sigmoidf_(gf) * c + sigmoidf_(gi) * tanhf(gg);
            float hn = sigmoidf_(go) * tanhf(cn);
            g_c1[r * HH + j] = cn;
            hout[r * HH + j] = hn;
        }
    }
}

// ---------------- logits = h1all @ w_out + b_out (round-2 proven) -------------
__global__ __launch_bounds__(256) void logits_gemm_kernel(
    const float* __restrict__ w_out, const float* __restrict__ b_out,
    float* __restrict__ temp)
{
    __shared__ float As[16][64];
    __shared__ float Bs[16][64];
    const int t = blockIdx.y;
    const int colBase = blockIdx.x * 64;
    const int tid = threadIdx.x;
    const int tx = tid & 15, ty = tid >> 4;
    const int aRow = tid >> 2, aK = (tid & 3) * 4;
    const int bRow = tid >> 4, bCol = (tid & 15) * 4;
    const bool fullTile = (colBase + 64 <= VV);

    const float* Aptr = g_h1all + ((size_t)t * 64 + aRow) * HH + aK;

    float acc[4][4] = {};
    for (int kt = 0; kt < 64; kt++) {
        __syncthreads();
        float4 a = *(const float4*)(Aptr + kt * 16);
        As[aK + 0][aRow] = a.x; As[aK + 1][aRow] = a.y;
        As[aK + 2][aRow] = a.z; As[aK + 3][aRow] = a.w;
        int col = colBase + bCol;
        const float* bp = w_out + (size_t)(kt * 16 + bRow) * VV + col;
        if (fullTile || col + 3 < VV) {
            *(float4*)&Bs[bRow][bCol] = *(const float4*)bp;
        } else {
#pragma unroll
            for (int q = 0; q < 4; q++)
                Bs[bRow][bCol + q] = (col + q < VV) ? bp[q] : 0.f;
        }
        __syncthreads();
#pragma unroll
        for (int k = 0; k < 16; k++) {
            float4 a4 = *(const float4*)&As[k][ty * 4];
            float4 b4 = *(const float4*)&Bs[k][tx * 4];
            acc[0][0] += a4.x * b4.x; acc[0][1] += a4.x * b4.y; acc[0][2] += a4.x * b4.z; acc[0][3] += a4.x * b4.w;
            acc[1][0] += a4.y * b4.x; acc[1][1] += a4.y * b4.y; acc[1][2] += a4.y * b4.z; acc[1][3] += a4.y * b4.w;
            acc[2][0] += a4.z * b4.x; acc[2][1] += a4.z * b4.y; acc[2][2] += a4.z * b4.z; acc[2][3] += a4.z * b4.w;
            acc[3][0] += a4.w * b4.x; acc[3][1] += a4.w * b4.y; acc[3][2] += a4.w * b4.z; acc[3][3] += a4.w * b4.w;
        }
    }
#pragma unroll
    for (int i = 0; i < 4; i++) {
        int b_ = ty * 4 + i;
#pragma unroll
        for (int j = 0; j < 4; j++) {
            int col = colBase + tx * 4 + j;
            if (col < VV)
                temp[((size_t)b_ * TS + t) * VV + col] = acc[i][j] + b_out[col];
        }
    }
}

// ---------------- loss: per-row -logp/length (deterministic) -----------------
__global__ __launch_bounds__(256) void loss_row_kernel(
    const float* __restrict__ temp, const int* __restrict__ sent,
    const int* __restrict__ length)
{
    __shared__ float sm_[256];
    __shared__ float ss[256];
    const int row = blockIdx.x;            // b*127 + t
    const int b = row / TS, t = row % TS;
    const float* x = temp + (size_t)row * VV;
    const int tid = threadIdx.x;

    float m = -1e30f, s = 0.f;
    for (int i = tid; i < VV; i += 256) {
        float v = x[i];
        float M = fmaxf(m, v);
        s = s * expf(m - M) + expf(v - M);
        m = M;
    }
    sm_[tid] = m; ss[tid] = s;
    __syncthreads();
    for (int w = 128; w > 0; w >>= 1) {
        if (tid < w) {
            float m2 = sm_[tid + w], s2 = ss[tid + w];
            float M = fmaxf(sm_[tid], m2);
            ss[tid] = ss[tid] * expf(sm_[tid] - M) + s2 * expf(m2 - M);
            sm_[tid] = M;
        }
        __syncthreads();
    }
    if (tid == 0) {
        int gt = sent[b * TT + t + 1];
        float lse = sm_[0] + logf(ss[0]);
        float res = 0.f;
        if (gt != 0) {
            float lp = x[gt] - lse;
            res = -lp / (float)length[b];
        }
        g_rowloss[row] = res;
    }
}

__global__ __launch_bounds__(256) void loss_final_kernel(float* __restrict__ out) {
    __shared__ float s[256];
    const int tid = threadIdx.x;
    float a = 0.f;
    for (int i = tid; i < TS * BB; i += 256) a += g_rowloss[i];
    s[tid] = a;
    __syncthreads();
    for (int w = 128; w > 0; w >>= 1) {
        if (tid < w) s[tid] += s[tid + w];
        __syncthreads();
    }
    if (tid == 0) out[0] = s[0];
}

// ---------------- host launcher ----------------------------------------------
extern "C" void kernel_launch(void* const* d_in, const int* in_sizes, int n_in,
                              void* d_out, int out_size)
{
    const int*   sent    = (const int*)d_in[0];
    const int*   length  = (const int*)d_in[1];
    const float* wordvec = (const float*)d_in[2];
    const float* w_ih0   = (const float*)d_in[3];
    const float* w_hh0   = (const float*)d_in[4];
    const float* b0      = (const float*)d_in[5];
    const float* w_ih1   = (const float*)d_in[6];
    const float* w_hh1   = (const float*)d_in[7];
    const float* b1      = (const float*)d_in[8];
    const float* w_out   = (const float*)d_in[9];
    const float* b_out   = (const float*)d_in[10];
    float* out = (float*)d_out;

    const long long TEMP_N = (long long)BB * TS * VV;
    int off = ((long long)out_size > TEMP_N) ? (int)((long long)out_size - TEMP_N) : 0;
    float* temp = out + off;

    init_state_kernel<<<256, 256>>>();
    pre0_gemm_kernel<<<dim3(64, TS), 256>>>(sent, wordvec, w_ih0, b0);
    for (int s = 0; s <= TS + 1; s++) {
        step3_kernel<<<384, 256>>>(s, w_hh0, w_ih1, w_hh1, b1);
    }
    logits_gemm_kernel<<<dim3(157, TS), 256>>>(w_out, b_out, temp);
    if (off > 0) {
        loss_row_kernel<<<TS * BB, 256>>>(temp, sent, length);
        loss_final_kernel<<<1, 256>>>(out);
    }
}

// round 9
// speedup vs baseline: 2.3409x; 2.3409x over previous
#include <cuda_runtime.h>
#include <cuda_bf16.h>
#include <math.h>

// Problem constants
#define BB 64
#define TT 128
#define TS 127          // timesteps = T-1
#define VV 10000
#define EE 300
#define HH 1024
#define G4 4096         // 4*H

#define GRID_N 296      // persistent grid: exactly 2 CTAs per SM on 148 SMs
#define NTASK 768       // gemm tasks per slot: L0 64x4=256, L1 64x8=512
#define NSLOT 128

// ---------------- scratch (static device memory; no allocations) -------------
__device__ float g_pre0[(size_t)TS * BB * G4];     // x@w_ih0 + b0, row = t*64+b
__device__ float g_h1all[(size_t)TS * BB * HH];    // all layer-1 hidden states
__device__ float g_h0buf[2][BB * HH];
__device__ float g_c0[BB * HH];
__device__ float g_c1[BB * HH];
__device__ float g_zero[BB * HH];                  // stays zero (never written)
__device__ float g_P0[4][BB * G4];                 // L0 K-chunk partials
__device__ float g_P1[8][BB * G4];                 // L1 K-chunk partials
__device__ float g_rowloss[TS * BB];
__device__ int   g_gctr[NSLOT];                    // per-slot task counters
__device__ unsigned g_bcnt;                        // grid barrier
__device__ unsigned g_bgen;

__device__ __forceinline__ float sigmoidf_(float x) {
    return 1.0f / (1.0f + expf(-x));
}

// ---------------- init: reset state every replay ------------------------------
__global__ void init_state_kernel() {
    int i = blockIdx.x * blockDim.x + threadIdx.x;
    if (i < BB * HH) { g_h0buf[0][i] = 0.f; g_c0[i] = 0.f; g_c1[i] = 0.f; g_zero[i] = 0.f; }
    if (i < NSLOT) g_gctr[i] = 0;
    if (i == 0) g_bcnt = 0;
}

// ---------------- grid barrier ------------------------------------------------
__device__ __forceinline__ void grid_bar() {
    __syncthreads();
    if (threadIdx.x == 0) {
        __threadfence();
        unsigned gen = *(volatile unsigned*)&g_bgen;
        if (atomicAdd(&g_bcnt, 1u) == GRID_N - 1) {
            *(volatile unsigned*)&g_bcnt = 0;
            __threadfence();
            *(volatile unsigned*)&g_bgen = gen + 1;
        } else {
            while (*(volatile unsigned*)&g_bgen == gen) { __nanosleep(64); }
        }
        __threadfence();
    }
    __syncthreads();
}

// ---------------- pre0 = gather(emb) @ w_ih0 + b0 ----------------------------
__global__ __launch_bounds__(256) void pre0_gemm_kernel(
    const int* __restrict__ sent, const float* __restrict__ wordvec,
    const float* __restrict__ w_ih0, const float* __restrict__ b0)
{
    __shared__ float As[4][64];
    __shared__ float Bs[4][64];
    const int t = blockIdx.y;
    const int colBase = blockIdx.x * 64;
    const int tid = threadIdx.x;
    const int tx = tid & 15, ty = tid >> 4;

    const float* arow = nullptr;
    if (tid < 64) {
        int token = sent[tid * TT + t];
        arow = wordvec + (size_t)token * EE;
    }
    const int bRow = tid >> 6, bCol = tid & 63;

    float acc[4][4] = {};
    for (int kt = 0; kt < 75; kt++) {
        __syncthreads();
        if (tid < 64) {
            float4 a = *(const float4*)(arow + kt * 4);
            As[0][tid] = a.x; As[1][tid] = a.y; As[2][tid] = a.z; As[3][tid] = a.w;
        }
        Bs[bRow][bCol] = w_ih0[(size_t)(kt * 4 + bRow) * G4 + colBase + bCol];
        __syncthreads();
#pragma unroll
        for (int k = 0; k < 4; k++) {
            float4 a4 = *(const float4*)&As[k][ty * 4];
            float4 b4 = *(const float4*)&Bs[k][tx * 4];
            acc[0][0] += a4.x * b4.x; acc[0][1] += a4.x * b4.y; acc[0][2] += a4.x * b4.z; acc[0][3] += a4.x * b4.w;
            acc[1][0] += a4.y * b4.x; acc[1][1] += a4.y * b4.y; acc[1][2] += a4.y * b4.z; acc[1][3] += a4.y * b4.w;
            acc[2][0] += a4.z * b4.x; acc[2][1] += a4.z * b4.y; acc[2][2] += a4.z * b4.z; acc[2][3] += a4.z * b4.w;
            acc[3][0] += a4.w * b4.x; acc[3][1] += a4.w * b4.y; acc[3][2] += a4.w * b4.z; acc[3][3] += a4.w * b4.w;
        }
    }
    float* dst = g_pre0 + ((size_t)t * 64) * G4 + colBase;
#pragma unroll
    for (int i = 0; i < 4; i++) {
        int b_ = ty * 4 + i;
#pragma unroll
        for (int j = 0; j < 4; j++) {
            int c = tx * 4 + j;
            dst[(size_t)b_ * G4 + c] = acc[i][j] + b0[colBase + c];
        }
    }
}

// ---------------- persistent recurrence kernel --------------------------------
// Slot s (0..127):
//  gemm phase (dynamic task queue, 768 tasks of 64x64xK256):
//    tasks [0,256):   P0[kc] = H0[s] chunk @ w_hh0 chunk       (valid s<=126)
//    tasks [256,768): P1[kc] = x/h chunk @ w_ih1/w_hh1 chunk   (valid s>=1)
//      kc<4: A = H0[s] (= new h0 of step s-1), W = w_ih1
//      kc>=4: A = H1[s-1] (h1all[s-2], zero for s==1), W = w_hh1
//  barrier; pointwise phase:
//    PW0 (s<=126): gates = sum P0[0..3] + pre0[s] -> c0, H0[s+1]
//    PW1 (s>=1):   gates = sum P1[0..7] + b1     -> c1, h1all[s-1]
//  barrier.
__global__ __launch_bounds__(256, 2) void recur_kernel(
    const float* __restrict__ w_hh0, const float* __restrict__ w_ih1,
    const float* __restrict__ w_hh1, const float* __restrict__ b1)
{
    __shared__ __align__(16) float As[16][64];
    __shared__ __align__(16) float Bs[16][64];
    __shared__ int s_task;

    const int tid = threadIdx.x;
    const int gthr = blockIdx.x * 256 + tid;

    const int aRow = tid >> 2, aK = (tid & 3) * 4;
    const int bRow = tid >> 4, bCol = (tid & 15) * 4;
    const int tx = tid & 15, ty = tid >> 4;

    for (int s = 0; s < NSLOT; s++) {
        // ---------------- gemm phase ----------------
        for (;;) {
            if (tid == 0) s_task = atomicAdd(&g_gctr[s], 1);
            __syncthreads();
            const int task = s_task;
            __syncthreads();
            if (task >= NTASK) break;

            const float* A; const float* W; float* P;
            bool ok = true;
            if (task < 256) {
                if (s > 126) ok = false;
                const int kc = task >> 6, ct = task & 63;
                A = g_h0buf[s & 1] + kc * 256;
                W = w_hh0 + (size_t)(kc * 256) * G4 + ct * 64;
                P = g_P0[kc] + ct * 64;
            } else {
                if (s < 1) ok = false;
                const int q = task - 256;
                const int kc = q >> 6, ct = q & 63;
                if (kc < 4) {
                    A = g_h0buf[s & 1] + kc * 256;
                    W = w_ih1 + (size_t)(kc * 256) * G4 + ct * 64;
                } else {
                    A = ((s >= 2) ? (g_h1all + (size_t)(s - 2) * BB * HH) : g_zero)
                        + (kc - 4) * 256;
                    W = w_hh1 + (size_t)((kc - 4) * 256) * G4 + ct * 64;
                }
                P = g_P1[kc] + ct * 64;
            }
            if (!ok) continue;

            float acc[4][4] = {};
            const float* Aptr = A + (size_t)aRow * HH + aK;
            const float* Wptr = W + (size_t)bRow * G4 + bCol;
            for (int kt = 0; kt < 16; kt++) {
                __syncthreads();
                float4 a = *(const float4*)(Aptr + kt * 16);
                As[aK + 0][aRow] = a.x; As[aK + 1][aRow] = a.y;
                As[aK + 2][aRow] = a.z; As[aK + 3][aRow] = a.w;
                *(float4*)&Bs[bRow][bCol] = *(const float4*)(Wptr + (size_t)kt * 16 * G4);
                __syncthreads();
#pragma unroll
                for (int k = 0; k < 16; k++) {
                    float4 a4 = *(const float4*)&As[k][ty * 4];
                    float4 b4 = *(const float4*)&Bs[k][tx * 4];
                    acc[0][0] += a4.x * b4.x; acc[0][1] += a4.x * b4.y; acc[0][2] += a4.x * b4.z; acc[0][3] += a4.x * b4.w;
                    acc[1][0] += a4.y * b4.x; acc[1][1] += a4.y * b4.y; acc[1][2] += a4.y * b4.z; acc[1][3] += a4.y * b4.w;
                    acc[2][0] += a4.z * b4.x; acc[2][1] += a4.z * b4.y; acc[2][2] += a4.z * b4.z; acc[2][3] += a4.z * b4.w;
                    acc[3][0] += a4.w * b4.x; acc[3][1] += a4.w * b4.y; acc[3][2] += a4.w * b4.z; acc[3][3] += a4.w * b4.w;
                }
            }
#pragma unroll
            for (int i = 0; i < 4; i++) {
                *(float4*)(P + (size_t)(ty * 4 + i) * G4 + tx * 4) =
                    make_float4(acc[i][0], acc[i][1], acc[i][2], acc[i][3]);
            }
        }
        grid_bar();

        // ---------------- pointwise phase ----------------
        if (gthr < BB * HH) {
            const int r = gthr >> 10, j = gthr & 1023;
            const size_t base = (size_t)r * G4;
            if (s <= 126) {
                const float* pre = g_pre0 + (size_t)s * BB * G4 + base;
                float gv[4];
#pragma unroll
                for (int g = 0; g < 4; g++) {
                    const int o = g * HH + j;
                    gv[g] = ((g_P0[0][base + o] + g_P0[1][base + o])
                           + (g_P0[2][base + o] + g_P0[3][base + o])) + pre[o];
                }
                float c  = g_c0[gthr];
                float cn = sigmoidf_(gv[1]) * c + sigmoidf_(gv[0]) * tanhf(gv[2]);
                float hn = sigmoidf_(gv[3]) * tanhf(cn);
                g_c0[gthr] = cn;
                g_h0buf[(s + 1) & 1][gthr] = hn;
            }
            if (s >= 1) {
                float gv[4];
#pragma unroll
                for (int g = 0; g < 4; g++) {
                    const int o = g * HH + j;
                    float a = (g_P1[0][base + o] + g_P1[1][base + o])
                            + (g_P1[2][base + o] + g_P1[3][base + o]);
                    float b = (g_P1[4][base + o] + g_P1[5][base + o])
                            + (g_P1[6][base + o] + g_P1[7][base + o]);
                    gv[g] = a + b + b1[o];
                }
                float c  = g_c1[gthr];
                float cn = sigmoidf_(gv[1]) * c + sigmoidf_(gv[0]) * tanhf(gv[2]);
                float hn = sigmoidf_(gv[3]) * tanhf(cn);
                g_c1[gthr] = cn;
                g_h1all[(size_t)(s - 1) * BB * HH + gthr] = hn;
            }
        }
        grid_bar();
    }
}

// ---------------- logits = h1all @ w_out + b_out (round-2 proven) -------------
__global__ __launch_bounds__(256) void logits_gemm_kernel(
    const float* __restrict__ w_out, const float* __restrict__ b_out,
    float* __restrict__ temp)
{
    __shared__ float As[16][64];
    __shared__ float Bs[16][64];
    const int t = blockIdx.y;
    const int colBase = blockIdx.x * 64;
    const int tid = threadIdx.x;
    const int tx = tid & 15, ty = tid >> 4;
    const int aRow = tid >> 2, aK = (tid & 3) * 4;
    const int bRow = tid >> 4, bCol = (tid & 15) * 4;
    const bool fullTile = (colBase + 64 <= VV);

    const float* Aptr = g_h1all + ((size_t)t * 64 + aRow) * HH + aK;

    float acc[4][4] = {};
    for (int kt = 0; kt < 64; kt++) {
        __syncthreads();
        float4 a = *(const float4*)(Aptr + kt * 16);
        As[aK + 0][aRow] = a.x; As[aK + 1][aRow] = a.y;
        As[aK + 2][aRow] = a.z; As[aK + 3][aRow] = a.w;
        int col = colBase + bCol;
        const float* bp = w_out + (size_t)(kt * 16 + bRow) * VV + col;
        if (fullTile || col + 3 < VV) {
            *(float4*)&Bs[bRow][bCol] = *(const float4*)bp;
        } else {
#pragma unroll
            for (int q = 0; q < 4; q++)
                Bs[bRow][bCol + q] = (col + q < VV) ? bp[q] : 0.f;
        }
        __syncthreads();
#pragma unroll
        for (int k = 0; k < 16; k++) {
            float4 a4 = *(const float4*)&As[k][ty * 4];
            float4 b4 = *(const float4*)&Bs[k][tx * 4];
            acc[0][0] += a4.x * b4.x; acc[0][1] += a4.x * b4.y; acc[0][2] += a4.x * b4.z; acc[0][3] += a4.x * b4.w;
            acc[1][0] += a4.y * b4.x; acc[1][1] += a4.y * b4.y; acc[1][2] += a4.y * b4.z; acc[1][3] += a4.y * b4.w;
            acc[2][0] += a4.z * b4.x; acc[2][1] += a4.z * b4.y; acc[2][2] += a4.z * b4.z; acc[2][3] += a4.z * b4.w;
            acc[3][0] += a4.w * b4.x; acc[3][1] += a4.w * b4.y; acc[3][2] += a4.w * b4.z; acc[3][3] += a4.w * b4.w;
        }
    }
#pragma unroll
    for (int i = 0; i < 4; i++) {
        int b_ = ty * 4 + i;
#pragma unroll
        for (int j = 0; j < 4; j++) {
            int col = colBase + tx * 4 + j;
            if (col < VV)
                temp[((size_t)b_ * TS + t) * VV + col] = acc[i][j] + b_out[col];
        }
    }
}

// ---------------- loss: per-row -logp/length (deterministic) -----------------
__global__ __launch_bounds__(256) void loss_row_kernel(
    const float* __restrict__ temp, const int* __restrict__ sent,
    const int* __restrict__ length)
{
    __shared__ float sm_[256];
    __shared__ float ss[256];
    const int row = blockIdx.x;            // b*127 + t
    const int b = row / TS, t = row % TS;
    const float* x = temp + (size_t)row * VV;
    const int tid = threadIdx.x;

    float m = -1e30f, s = 0.f;
    for (int i = tid; i < VV; i += 256) {
        float v = x[i];
        float M = fmaxf(m, v);
        s = s * expf(m - M) + expf(v - M);
        m = M;
    }
    sm_[tid] = m; ss[tid] = s;
    __syncthreads();
    for (int w = 128; w > 0; w >>= 1) {
        if (tid < w) {
            float m2 = sm_[tid + w], s2 = ss[tid + w];
            float M = fmaxf(sm_[tid], m2);
            ss[tid] = ss[tid] * expf(sm_[tid] - M) + s2 * expf(m2 - M);
            sm_[tid] = M;
        }
        __syncthreads();
    }
    if (tid == 0) {
        int gt = sent[b * TT + t + 1];
        float lse = sm_[0] + logf(ss[0]);
        float res = 0.f;
        if (gt != 0) {
            float lp = x[gt] - lse;
            res = -lp / (float)length[b];
        }
        g_rowloss[row] = res;
    }
}

__global__ __launch_bounds__(256) void loss_final_kernel(float* __restrict__ out) {
    __shared__ float s[256];
    const int tid = threadIdx.x;
    float a = 0.f;
    for (int i = tid; i < TS * BB; i += 256) a += g_rowloss[i];
    s[tid] = a;
    __syncthreads();
    for (int w = 128; w > 0; w >>= 1) {
        if (tid < w) s[tid] += s[tid + w];
        __syncthreads();
    }
    if (tid == 0) out[0] = s[0];
}

// ---------------- host launcher ----------------------------------------------
extern "C" void kernel_launch(void* const* d_in, const int* in_sizes, int n_in,
                              void* d_out, int out_size)
{
    const int*   sent    = (const int*)d_in[0];
    const int*   length  = (const int*)d_in[1];
    const float* wordvec = (const float*)d_in[2];
    const float* w_ih0   = (const float*)d_in[3];
    const float* w_hh0   = (const float*)d_in[4];
    const float* b0      = (const float*)d_in[5];
    const float* w_ih1   = (const float*)d_in[6];
    const float* w_hh1   = (const float*)d_in[7];
    const float* b1      = (const float*)d_in[8];
    const float* w_out   = (const float*)d_in[9];
    const float* b_out   = (const float*)d_in[10];
    float* out = (float*)d_out;

    const long long TEMP_N = (long long)BB * TS * VV;
    int off = ((long long)out_size > TEMP_N) ? (int)((long long)out_size - TEMP_N) : 0;
    float* temp = out + off;

    init_state_kernel<<<256, 256>>>();
    pre0_gemm_kernel<<<dim3(64, TS), 256>>>(sent, wordvec, w_ih0, b0);
    recur_kernel<<<GRID_N, 256>>>(w_hh0, w_ih1, w_hh1, b1);
    logits_gemm_kernel<<<dim3(157, TS), 256>>>(w_out, b_out, temp);
    if (off > 0) {
        loss_row_kernel<<<TS * BB, 256>>>(temp, sent, length);
        loss_final_kernel<<<1, 256>>>(out);
    }
}

// round 12
// speedup vs baseline: 2.5290x; 1.0803x over previous
#include <cuda_runtime.h>
#include <cuda_bf16.h>
#include <math.h>

// Problem constants
#define BB 64
#define TT 128
#define TS 127          // timesteps = T-1
#define VV 10000
#define EE 300
#define HH 1024
#define G4 4096         // 4*H

#define GRID_N 296      // persistent grid: exactly 2 CTAs per SM on 148 SMs
#define NTASK 768       // gemm tasks per slot: L0 64x4=256, L1 64x8=512
#define NSLOT 128
#define SPAD 68         // padded smem row (floats), 16B-aligned, conflict-reduced

typedef unsigned long long u64;

// ---------------- scratch (static device memory; no allocations) -------------
__device__ float g_pre0[(size_t)TS * BB * G4];     // x@w_ih0 + b0, row = t*64+b
__device__ float g_h1all[(size_t)TS * BB * HH];    // all layer-1 hidden states
__device__ float g_h0buf[2][BB * HH];
__device__ float g_c0[BB * HH];
__device__ float g_c1[BB * HH];
__device__ float g_zero[BB * HH];                  // stays zero (never written)
__device__ float g_P0[4][BB * G4];                 // L0 K-chunk partials
__device__ float g_P1[8][BB * G4];                 // L1 K-chunk partials
__device__ float g_rowloss[TS * BB];
__device__ int   g_gctr[NSLOT];                    // per-slot task counters
__device__ unsigned g_bcnt;                        // grid barrier
__device__ unsigned g_bgen;

__device__ __forceinline__ float sigmoidf_(float x) {
    return 1.0f / (1.0f + expf(-x));
}
__device__ __forceinline__ u64 fma2_(u64 a, u64 b, u64 c) {
    u64 d; asm("fma.rn.f32x2 %0, %1, %2, %3;" : "=l"(d) : "l"(a), "l"(b), "l"(c));
    return d;
}
__device__ __forceinline__ u64 pack2_(float x) {
    u64 d; asm("mov.b64 %0, {%1, %1};" : "=l"(d) : "f"(x));
    return d;
}
__device__ __forceinline__ float2 unpack2_(u64 a) {
    float2 f; asm("mov.b64 {%0, %1}, %2;" : "=f"(f.x), "=f"(f.y) : "l"(a));
    return f;
}

// ---------------- init: reset state every replay ------------------------------
__global__ void init_state_kernel() {
    int i = blockIdx.x * blockDim.x + threadIdx.x;
    if (i < BB * HH) { g_h0buf[0][i] = 0.f; g_c0[i] = 0.f; g_c1[i] = 0.f; g_zero[i] = 0.f; }
    if (i < NSLOT) g_gctr[i] = 0;
    if (i == 0) g_bcnt = 0;
}

// ---------------- grid barrier ------------------------------------------------
__device__ __forceinline__ void grid_bar() {
    __syncthreads();
    if (threadIdx.x == 0) {
        __threadfence();
        unsigned gen = *(volatile unsigned*)&g_bgen;
        if (atomicAdd(&g_bcnt, 1u) == GRID_N - 1) {
            *(volatile unsigned*)&g_bcnt = 0;
            __threadfence();
            *(volatile unsigned*)&g_bgen = gen + 1;
        } else {
            while (*(volatile unsigned*)&g_bgen == gen) { __nanosleep(64); }
        }
        __threadfence();
    }
    __syncthreads();
}

// ---------------- pre0 = gather(emb) @ w_ih0 + b0 ----------------------------
__global__ __launch_bounds__(256) void pre0_gemm_kernel(
    const int* __restrict__ sent, const float* __restrict__ wordvec,
    const float* __restrict__ w_ih0, const float* __restrict__ b0)
{
    __shared__ float As[4][64];
    __shared__ float Bs[4][64];
    const int t = blockIdx.y;
    const int colBase = blockIdx.x * 64;
    const int tid = threadIdx.x;
    const int tx = tid & 15, ty = tid >> 4;

    const float* arow = nullptr;
    if (tid < 64) {
        int token = sent[tid * TT + t];
        arow = wordvec + (size_t)token * EE;
    }
    const int bRow = tid >> 6, bCol = tid & 63;

    float acc[4][4] = {};
    for (int kt = 0; kt < 75; kt++) {
        __syncthreads();
        if (tid < 64) {
            float4 a = *(const float4*)(arow + kt * 4);
            As[0][tid] = a.x; As[1][tid] = a.y; As[2][tid] = a.z; As[3][tid] = a.w;
        }
        Bs[bRow][bCol] = w_ih0[(size_t)(kt * 4 + bRow) * G4 + colBase + bCol];
        __syncthreads();
#pragma unroll
        for (int k = 0; k < 4; k++) {
            float4 a4 = *(const float4*)&As[k][ty * 4];
            float4 b4 = *(const float4*)&Bs[k][tx * 4];
            acc[0][0] += a4.x * b4.x; acc[0][1] += a4.x * b4.y; acc[0][2] += a4.x * b4.z; acc[0][3] += a4.x * b4.w;
            acc[1][0] += a4.y * b4.x; acc[1][1] += a4.y * b4.y; acc[1][2] += a4.y * b4.z; acc[1][3] += a4.y * b4.w;
            acc[2][0] += a4.z * b4.x; acc[2][1] += a4.z * b4.y; acc[2][2] += a4.z * b4.z; acc[2][3] += a4.z * b4.w;
            acc[3][0] += a4.w * b4.x; acc[3][1] += a4.w * b4.y; acc[3][2] += a4.w * b4.z; acc[3][3] += a4.w * b4.w;
        }
    }
    float* dst = g_pre0 + ((size_t)t * 64) * G4 + colBase;
#pragma unroll
    for (int i = 0; i < 4; i++) {
        int b_ = ty * 4 + i;
#pragma unroll
        for (int j = 0; j < 4; j++) {
            int c = tx * 4 + j;
            dst[(size_t)b_ * G4 + c] = acc[i][j] + b0[colBase + c];
        }
    }
}

// ---------------- persistent recurrence kernel --------------------------------
// Slot s (0..127), dynamic task queue, 768 tasks of 64x64xK256 per slot.
// Inner GEMM: f32x2 row-pair accumulation (8 FFMA2 / 2 LDS / 4 MOV per thread/k).
__global__ __launch_bounds__(256, 2) void recur_kernel(
    const float* __restrict__ w_hh0, const float* __restrict__ w_ih1,
    const float* __restrict__ w_hh1, const float* __restrict__ b1)
{
    __shared__ __align__(16) float As[16][SPAD];
    __shared__ __align__(16) float Bs[16][SPAD];
    __shared__ int s_task;

    const int tid = threadIdx.x;
    const int gthr = blockIdx.x * 256 + tid;

    const int aRow = tid >> 2, aK = (tid & 3) * 4;
    const int bRow = tid >> 4, bCol = (tid & 15) * 4;
    const int tx = tid & 15, ty = tid >> 4;
    const int r0 = ty * 4, c0 = tx * 4;

    for (int s = 0; s < NSLOT; s++) {
        // ---------------- gemm phase ----------------
        for (;;) {
            if (tid == 0) s_task = atomicAdd(&g_gctr[s], 1);
            __syncthreads();
            const int task = s_task;
            __syncthreads();
            if (task >= NTASK) break;

            const float* A; const float* W; float* P;
            bool ok = true;
            if (task < 256) {
                if (s > 126) ok = false;
                const int kc = task >> 6, ct = task & 63;
                A = g_h0buf[s & 1] + kc * 256;
                W = w_hh0 + (size_t)(kc * 256) * G4 + ct * 64;
                P = g_P0[kc] + ct * 64;
            } else {
                if (s < 1) ok = false;
                const int q = task - 256;
                const int kc = q >> 6, ct = q & 63;
                if (kc < 4) {
                    A = g_h0buf[s & 1] + kc * 256;
                    W = w_ih1 + (size_t)(kc * 256) * G4 + ct * 64;
                } else {
                    A = ((s >= 2) ? (g_h1all + (size_t)(s - 2) * BB * HH) : g_zero)
                        + (kc - 4) * 256;
                    W = w_hh1 + (size_t)((kc - 4) * 256) * G4 + ct * 64;
                }
                P = g_P1[kc] + ct * 64;
            }
            if (!ok) continue;

            const float* Aptr = A + (size_t)aRow * HH + aK;
            const float* Wptr = W + (size_t)bRow * G4 + bCol;

            u64 acc[2][4] = {};
            float4 pa = *(const float4*)(Aptr);
            float4 pb = *(const float4*)(Wptr);

            for (int kt = 0; kt < 16; kt++) {
                __syncthreads();
                As[aK + 0][aRow] = pa.x; As[aK + 1][aRow] = pa.y;
                As[aK + 2][aRow] = pa.z; As[aK + 3][aRow] = pa.w;
                *(float4*)&Bs[bRow][bCol] = pb;
                if (kt < 15) {
                    pa = *(const float4*)(Aptr + (kt + 1) * 16);
                    pb = *(const float4*)(Wptr + (size_t)(kt + 1) * 16 * G4);
                }
                __syncthreads();
#pragma unroll
                for (int k = 0; k < 16; k++) {
                    ulonglong2 ap = *(const ulonglong2*)&As[k][r0];
                    float4 b4 = *(const float4*)&Bs[k][c0];
                    u64 w0 = pack2_(b4.x), w1 = pack2_(b4.y);
                    u64 w2 = pack2_(b4.z), w3 = pack2_(b4.w);
                    acc[0][0] = fma2_(ap.x, w0, acc[0][0]);
                    acc[0][1] = fma2_(ap.x, w1, acc[0][1]);
                    acc[0][2] = fma2_(ap.x, w2, acc[0][2]);
                    acc[0][3] = fma2_(ap.x, w3, acc[0][3]);
                    acc[1][0] = fma2_(ap.y, w0, acc[1][0]);
                    acc[1][1] = fma2_(ap.y, w1, acc[1][1]);
                    acc[1][2] = fma2_(ap.y, w2, acc[1][2]);
                    acc[1][3] = fma2_(ap.y, w3, acc[1][3]);
                }
            }

            // epilogue: rows r0..r0+3 (pairs), cols c0..c0+3
#pragma unroll
            for (int p = 0; p < 2; p++) {
                float2 v0 = unpack2_(acc[p][0]);
                float2 v1 = unpack2_(acc[p][1]);
                float2 v2 = unpack2_(acc[p][2]);
                float2 v3 = unpack2_(acc[p][3]);
                *(float4*)(P + (size_t)(r0 + 2 * p) * G4 + c0) =
                    make_float4(v0.x, v1.x, v2.x, v3.x);
                *(float4*)(P + (size_t)(r0 + 2 * p + 1) * G4 + c0) =
                    make_float4(v0.y, v1.y, v2.y, v3.y);
            }
        }
        grid_bar();

        // ---------------- pointwise phase ----------------
        if (gthr < BB * HH) {
            const int r = gthr >> 10, j = gthr & 1023;
            const size_t base = (size_t)r * G4;
            if (s <= 126) {
                const float* pre = g_pre0 + (size_t)s * BB * G4 + base;
                float gv[4];
#pragma unroll
                for (int g = 0; g < 4; g++) {
                    const int o = g * HH + j;
                    gv[g] = ((g_P0[0][base + o] + g_P0[1][base + o])
                           + (g_P0[2][base + o] + g_P0[3][base + o])) + pre[o];
                }
                float c  = g_c0[gthr];
                float cn = sigmoidf_(gv[1]) * c + sigmoidf_(gv[0]) * tanhf(gv[2]);
                float hn = sigmoidf_(gv[3]) * tanhf(cn);
                g_c0[gthr] = cn;
                g_h0buf[(s + 1) & 1][gthr] = hn;
            }
            if (s >= 1) {
                float gv[4];
#pragma unroll
                for (int g = 0; g < 4; g++) {
                    const int o = g * HH + j;
                    float a = (g_P1[0][base + o] + g_P1[1][base + o])
                            + (g_P1[2][base + o] + g_P1[3][base + o]);
                    float b = (g_P1[4][base + o] + g_P1[5][base + o])
                            + (g_P1[6][base + o] + g_P1[7][base + o]);
                    gv[g] = a + b + b1[o];
                }
                float c  = g_c1[gthr];
                float cn = sigmoidf_(gv[1]) * c + sigmoidf_(gv[0]) * tanhf(gv[2]);
                float hn = sigmoidf_(gv[3]) * tanhf(cn);
                g_c1[gthr] = cn;
                g_h1all[(size_t)(s - 1) * BB * HH + gthr] = hn;
            }
        }
        grid_bar();
    }
}

// ---------------- logits = h1all @ w_out + b_out (round-2 proven) -------------
__global__ __launch_bounds__(256) void logits_gemm_kernel(
    const float* __restrict__ w_out, const float* __restrict__ b_out,
    float* __restrict__ temp)
{
    __shared__ float As[16][64];
    __shared__ float Bs[16][64];
    const int t = blockIdx.y;
    const int colBase = blockIdx.x * 64;
    const int tid = threadIdx.x;
    const int tx = tid & 15, ty = tid >> 4;
    const int aRow = tid >> 2, aK = (tid & 3) * 4;
    const int bRow = tid >> 4, bCol = (tid & 15) * 4;
    const bool fullTile = (colBase + 64 <= VV);

    const float* Aptr = g_h1all + ((size_t)t * 64 + aRow) * HH + aK;

    float acc[4][4] = {};
    for (int kt = 0; kt < 64; kt++) {
        __syncthreads();
        float4 a = *(const float4*)(Aptr + kt * 16);
        As[aK + 0][aRow] = a.x; As[aK + 1][aRow] = a.y;
        As[aK + 2][aRow] = a.z; As[aK + 3][aRow] = a.w;
        int col = colBase + bCol;
        const float* bp = w_out + (size_t)(kt * 16 + bRow) * VV + col;
        if (fullTile || col + 3 < VV) {
            *(float4*)&Bs[bRow][bCol] = *(const float4*)bp;
        } else {
#pragma unroll
            for (int q = 0; q < 4; q++)
                Bs[bRow][bCol + q] = (col + q < VV) ? bp[q] : 0.f;
        }
        __syncthreads();
#pragma unroll
        for (int k = 0; k < 16; k++) {
            float4 a4 = *(const float4*)&As[k][ty * 4];
            float4 b4 = *(const float4*)&Bs[k][tx * 4];
            acc[0][0] += a4.x * b4.x; acc[0][1] += a4.x * b4.y; acc[0][2] += a4.x * b4.z; acc[0][3] += a4.x * b4.w;
            acc[1][0] += a4.y * b4.x; acc[1][1] += a4.y * b4.y; acc[1][2] += a4.y * b4.z; acc[1][3] += a4.y * b4.w;
            acc[2][0] += a4.z * b4.x; acc[2][1] += a4.z * b4.y; acc[2][2] += a4.z * b4.z; acc[2][3] += a4.z * b4.w;
            acc[3][0] += a4.w * b4.x; acc[3][1] += a4.w * b4.y; acc[3][2] += a4.w * b4.z; acc[3][3] += a4.w * b4.w;
        }
    }
#pragma unroll
    for (int i = 0; i < 4; i++) {
        int b_ = ty * 4 + i;
#pragma unroll
        for (int j = 0; j < 4; j++) {
            int col = colBase + tx * 4 + j;
            if (col < VV)
                temp[((size_t)b_ * TS + t) * VV + col] = acc[i][j] + b_out[col];
        }
    }
}

// ---------------- loss: per-row -logp/length (deterministic) -----------------
__global__ __launch_bounds__(256) void loss_row_kernel(
    const float* __restrict__ temp, const int* __restrict__ sent,
    const int* __restrict__ length)
{
    __shared__ float sm_[256];
    __shared__ float ss[256];
    const int row = blockIdx.x;            // b*127 + t
    const int b = row / TS, t = row % TS;
    const float* x = temp + (size_t)row * VV;
    const int tid = threadIdx.x;

    float m = -1e30f, s = 0.f;
    for (int i = tid; i < VV; i += 256) {
        float v = x[i];
        float M = fmaxf(m, v);
        s = s * expf(m - M) + expf(v - M);
        m = M;
    }
    sm_[tid] = m; ss[tid] = s;
    __syncthreads();
    for (int w = 128; w > 0; w >>= 1) {
        if (tid < w) {
            float m2 = sm_[tid + w], s2 = ss[tid + w];
            float M = fmaxf(sm_[tid], m2);
            ss[tid] = ss[tid] * expf(sm_[tid] - M) + s2 * expf(m2 - M);
            sm_[tid] = M;
        }
        __syncthreads();
    }
    if (tid == 0) {
        int gt = sent[b * TT + t + 1];
        float lse = sm_[0] + logf(ss[0]);
        float res = 0.f;
        if (gt != 0) {
            float lp = x[gt] - lse;
            res = -lp / (float)length[b];
        }
        g_rowloss[row] = res;
    }
}

__global__ __launch_bounds__(256) void loss_final_kernel(float* __restrict__ out) {
    __shared__ float s[256];
    const int tid = threadIdx.x;
    float a = 0.f;
    for (int i = tid; i < TS * BB; i += 256) a += g_rowloss[i];
    s[tid] = a;
    __syncthreads();
    for (int w = 128; w > 0; w >>= 1) {
        if (tid < w) s[tid] += s[tid + w];
        __syncthreads();
    }
    if (tid == 0) out[0] = s[0];
}

// ---------------- host launcher ----------------------------------------------
extern "C" void kernel_launch(void* const* d_in, const int* in_sizes, int n_in,
                              void* d_out, int out_size)
{
    const int*   sent    = (const int*)d_in[0];
    const int*   length  = (const int*)d_in[1];
    const float* wordvec = (const float*)d_in[2];
    const float* w_ih0   = (const float*)d_in[3];
    const float* w_hh0   = (const float*)d_in[4];
    const float* b0      = (const float*)d_in[5];
    const float* w_ih1   = (const float*)d_in[6];
    const float* w_hh1   = (const float*)d_in[7];
    const float* b1      = (const float*)d_in[8];
    const float* w_out   = (const float*)d_in[9];
    const float* b_out   = (const float*)d_in[10];
    float* out = (float*)d_out;

    const long long TEMP_N = (long long)BB * TS * VV;
    int off = ((long long)out_size > TEMP_N) ? (int)((long long)out_size - TEMP_N) : 0;
    float* temp = out + off;

    init_state_kernel<<<256, 256>>>();
    pre0_gemm_kernel<<<dim3(64, TS), 256>>>(sent, wordvec, w_ih0, b0);
    recur_kernel<<<GRID_N, 256>>>(w_hh0, w_ih1, w_hh1, b1);
    logits_gemm_kernel<<<dim3(157, TS), 256>>>(w_out, b_out, temp);
    if (off > 0) {
        loss_row_kernel<<<TS * BB, 256>>>(temp, sent, length);
        loss_final_kernel<<<1, 256>>>(out);
    }
}